// round 5
// baseline (speedup 1.0000x reference)
#include <cuda_runtime.h>
#include <cstdint>

#define B_    32
#define T_    128
#define NIN_  64
#define H_    512
#define DMAX_ 50
#define K_    4
#define HB_   128           // h per block
#define NHB_  (H_/HB_)      // 4 h-tiles
#define THREADS 512
#define NBLK  (B_ * NHB_)   // 128

#define TPAD  132                 // 128 real rows + 4 per-slot dump rows
#define ICOPY (TPAD * HB_)        // floats per I copy (16896)

// deterministic partial sums: [b][hb][k]
__device__ float g_partials[B_ * NHB_ * K_];
__device__ unsigned int g_counter = 0;

__global__ __launch_bounds__(THREADS, 1)
void snn_main_kernel(const float* __restrict__ spikes,      // [B,T,NIN]
                     const float* __restrict__ w_ih,        // [H,NIN]
                     const float* __restrict__ delay_raw,   // [H,NIN]
                     const float* __restrict__ w_read,      // [H]
                     const float* __restrict__ b_read,      // scalar
                     const float* __restrict__ slot_mask,   // [K,T]
                     float* __restrict__ out)               // [B,K]
{
    extern __shared__ char smem_raw[];
    float*  I_sh    = (float*)smem_raw;                       // 2 copies [TPAD][HB]: 135168 B
    float2* wp_sh   = (float2*)(I_sh + 2*ICOPY);              // [NIN][HB]  65536 B
    unsigned char* s_sh = (unsigned char*)(wp_sh + NIN_*HB_); // [NIN][HB]   8192 B
    unsigned int* maskA = (unsigned int*)(s_sh + NIN_*HB_);   // [T][2]      1024 B
    unsigned long long* colbits = (unsigned long long*)(maskA + T_*2); // [2][NIN] 1024 B
    float*  mask_sh = (float*)(colbits + 2*NIN_);             // [K][T]      2048 B
    float*  red     = mask_sh + K_*T_;                        // 16 floats

    __shared__ int is_last;

    const int tid = threadIdx.x;
    const int hb  = blockIdx.x;
    const int b   = blockIdx.y;

    // ---- zero both I copies (incl. dump rows) ----
    for (int r = tid; r < 2*ICOPY; r += THREADS)
        I_sh[r] = 0.f;

    // slot mask -> smem
    for (int j = tid; j < K_*T_; j += THREADS) mask_sh[j] = slot_mask[j];

    // ---- Phase A: per-timestep 64-bit active-input masks (deterministic ballots) ----
    {
        const float* xb = spikes + (size_t)b * T_ * NIN_;
        #pragma unroll
        for (int rep = 0; rep < (T_*NIN_)/THREADS; rep++) {
            int idx = rep*THREADS + tid;           // t = idx>>6, i = idx&63
            float v = xb[idx];
            unsigned int ball = __ballot_sync(0xFFFFFFFFu, v != 0.f);
            if ((tid & 31) == 0) {
                int t = idx >> 6;
                int half = (idx >> 5) & 1;
                maskA[t*2 + half] = ball;
            }
        }
    }

    // ---- Phase 1c: tap params, transposed [i][h] layout ----
    {
        const int gbase = hb * HB_ * NIN_;
        #pragma unroll
        for (int rep = 0; rep < (HB_*NIN_)/THREADS; rep++) {
            int idx = rep*THREADS + tid;
            int hh = idx >> 6;
            int ii = idx & 63;
            float raw  = delay_raw[gbase + idx];
            float w    = w_ih[gbase + idx];
            float d    = (float)DMAX_ / (1.f + expf(-raw));  // sigmoid * DMAX
            float d0   = floorf(d);
            float frac = d - d0;
            int   s0   = (int)d0 + 1;                        // read-before-insert => +1
            wp_sh[ii*HB_ + hh] = make_float2(w*(1.f-frac), w*frac);
            s_sh [ii*HB_ + hh] = (unsigned char)s0;
        }
    }
    __syncthreads();

    // ---- Phase A2: bit-transpose -> per-column 64-bit masks (broadcast LDS) ----
    if (tid < 2*NIN_) {
        int i    = tid & (NIN_-1);
        int half = tid >> 6;               // t-half: bits t' in [half*64, half*64+64)
        int wsel = i >> 5;
        int shft = i & 31;
        unsigned long long bits = 0ull;
        #pragma unroll
        for (int tb = 0; tb < 64; tb++) {
            unsigned int mw = maskA[(half*64 + tb)*2 + wsel];
            bits |= (unsigned long long)((mw >> shft) & 1u) << tb;
        }
        colbits[half*NIN_ + i] = bits;
    }
    __syncthreads();

    // ---- Phase B: column-driven batched scatter ----
    // Per column i, shift s is fixed per lane -> tap targets t'+s are pairwise
    // DISTINCT across the column's set bits. Batch 4 events: LDSx4 / FADDx4 / STSx4
    // (pipelined loads). Overflow + absent-bit slots clamp to per-slot dump rows
    // 128+j (distinct within batch). Tap1 sub-batch follows tap0 in program order
    // (compiler keeps shared-mem order -> safe under any aliasing between them).
    if (tid < 2*HB_) {
        const int grp = tid >> 7;                 // 0: columns 0..31, 1: columns 32..63
        const int h   = tid & (HB_-1);
        float* __restrict__ Ic = I_sh + grp * ICOPY;
        #pragma unroll 1
        for (int ci = 0; ci < 32; ci++) {
            const int i = grp*32 + ci;
            const float2 w  = wp_sh[i*HB_ + h];
            const int   s0  = (int)s_sh[i*HB_ + h];
            const int   s1  = min(s0 + 1, DMAX_ + 1);
            #pragma unroll
            for (int half = 0; half < 2; half++) {
                unsigned long long m = colbits[half*NIN_ + i];
                const int tb = half * 64;
                while (m) {
                    int b0 = __ffsll(m) - 1;            m &= m - 1;
                    int b1 = m ? __ffsll(m) - 1 : 255;  m &= m - 1;
                    int b2 = m ? __ffsll(m) - 1 : 255;  m &= m - 1;
                    int b3 = m ? __ffsll(m) - 1 : 255;  m &= m - 1;
                    // tap0 sub-batch (rows distinct by construction)
                    int r0 = min(b0 + tb + s0, T_ + 0);
                    int r1 = min(b1 + tb + s0, T_ + 1);
                    int r2 = min(b2 + tb + s0, T_ + 2);
                    int r3 = min(b3 + tb + s0, T_ + 3);
                    float a0 = Ic[r0*HB_ + h];
                    float a1 = Ic[r1*HB_ + h];
                    float a2 = Ic[r2*HB_ + h];
                    float a3 = Ic[r3*HB_ + h];
                    Ic[r0*HB_ + h] = a0 + w.x;
                    Ic[r1*HB_ + h] = a1 + w.x;
                    Ic[r2*HB_ + h] = a2 + w.x;
                    Ic[r3*HB_ + h] = a3 + w.x;
                    // tap1 sub-batch
                    int q0 = min(b0 + tb + s1, T_ + 0);
                    int q1 = min(b1 + tb + s1, T_ + 1);
                    int q2 = min(b2 + tb + s1, T_ + 2);
                    int q3 = min(b3 + tb + s1, T_ + 3);
                    float c0 = Ic[q0*HB_ + h];
                    float c1 = Ic[q1*HB_ + h];
                    float c2 = Ic[q2*HB_ + h];
                    float c3 = Ic[q3*HB_ + h];
                    Ic[q0*HB_ + h] = c0 + w.y;
                    Ic[q1*HB_ + h] = c1 + w.y;
                    Ic[q2*HB_ + h] = c2 + w.y;
                    Ic[q3*HB_ + h] = c3 + w.y;
                }
            }
        }
    }
    __syncthreads();

    // ---- Phase 3: LIF scan + masked accumulation (threads 0..127 = h) ----
    if (tid < HB_) {
        float v = 0.f;       // VRESET
        int   ref = 0;
        float a0 = 0.f, a1 = 0.f, a2 = 0.f, a3 = 0.f;
        #pragma unroll
        for (int t = 0; t < T_; t++) {
            float I  = I_sh[t*HB_ + tid] + I_sh[ICOPY + t*HB_ + tid];
            bool  nr = (ref <= 0);
            float vn = nr ? (v + 0.1f * (I - v)) : v;            // DT/TAU=0.1, VRESET=0
            float spk = (nr && (vn - 1.0f >= 0.f)) ? 1.f : 0.f;  // spike_fn(v-THR)*not_ref
            v   = (spk != 0.f) ? 0.f : vn;
            ref = (spk != 0.f) ? 2 : max(ref - 1, 0);
            a0 += spk * mask_sh[0*T_ + t];
            a1 += spk * mask_sh[1*T_ + t];
            a2 += spk * mask_sh[2*T_ + t];
            a3 += spk * mask_sh[3*T_ + t];
        }

        float wr = w_read[hb*HB_ + tid];
        float c0 = a0 * wr, c1 = a1 * wr, c2 = a2 * wr, c3 = a3 * wr;
        #pragma unroll
        for (int off = 16; off; off >>= 1) {
            c0 += __shfl_down_sync(0xFFFFFFFFu, c0, off);
            c1 += __shfl_down_sync(0xFFFFFFFFu, c1, off);
            c2 += __shfl_down_sync(0xFFFFFFFFu, c2, off);
            c3 += __shfl_down_sync(0xFFFFFFFFu, c3, off);
        }
        int lane = tid & 31, warp = tid >> 5;
        if (lane == 0) {
            red[warp*4 + 0] = c0;
            red[warp*4 + 1] = c1;
            red[warp*4 + 2] = c2;
            red[warp*4 + 3] = c3;
        }
    }
    __syncthreads();
    if (tid < K_) {
        float s = red[tid] + red[4 + tid] + red[8 + tid] + red[12 + tid];
        g_partials[(b*NHB_ + hb)*K_ + tid] = s;
    }
    __syncthreads();

    // ---- fused deterministic final reduction: last block writes output ----
    if (tid == 0) {
        __threadfence();
        unsigned int done = atomicAdd(&g_counter, 1u);
        is_last = (done == NBLK - 1) ? 1 : 0;
    }
    __syncthreads();
    if (is_last) {
        if (tid == 0) g_counter = 0;   // reset for next graph replay
        __threadfence();
        if (tid < B_ * K_) {
            int bb = tid >> 2, kk = tid & 3;
            float s = b_read[0];
            #pragma unroll
            for (int h2 = 0; h2 < NHB_; h2++)
                s += __ldcg(&g_partials[(bb*NHB_ + h2)*K_ + kk]);
            out[bb*K_ + kk] = s;
        }
    }
}

extern "C" void kernel_launch(void* const* d_in, const int* in_sizes, int n_in,
                              void* d_out, int out_size)
{
    (void)in_sizes; (void)n_in; (void)out_size;
    const float* spikes    = (const float*)d_in[0];   // [32,128,64]
    const float* w_ih      = (const float*)d_in[1];   // [512,64]
    const float* delay_raw = (const float*)d_in[2];   // [512,64]
    const float* w_read    = (const float*)d_in[3];   // [512]
    const float* b_read    = (const float*)d_in[4];   // scalar
    const float* slot_mask = (const float*)d_in[5];   // [4,128]

    const size_t SMEM = (size_t)2*ICOPY*4             // 2 I copies   135168
                      + (size_t)NIN_*HB_*8            // wp (float2)   65536
                      + (size_t)NIN_*HB_              // s (u8)         8192
                      + (size_t)T_*2*4                // maskA          1024
                      + (size_t)2*NIN_*8              // colbits        1024
                      + (size_t)K_*T_*4               // slot mask      2048
                      + 16*4;                         // red
    cudaFuncSetAttribute(snn_main_kernel,
                         cudaFuncAttributeMaxDynamicSharedMemorySize, (int)SMEM);

    dim3 grid(NHB_, B_);
    snn_main_kernel<<<grid, THREADS, SMEM>>>(spikes, w_ih, delay_raw, w_read,
                                             b_read, slot_mask, (float*)d_out);
}

// round 6
// speedup vs baseline: 1.0706x; 1.0706x over previous
#include <cuda_runtime.h>
#include <cstdint>

#define B_    32
#define T_    128
#define NIN_  64
#define H_    512
#define DMAX_ 50
#define K_    4
#define HB_   128           // h per block
#define NHB_  (H_/HB_)      // 4 h-tiles
#define THREADS 256
#define NBLK  (B_ * NHB_)   // 128

#define TPAD  132                 // 128 real rows + 4 per-slot dump rows
#define ICOPY (TPAD * HB_)        // floats per I copy (16896)

// deterministic partial sums: [b][hb][k]
__device__ float g_partials[B_ * NHB_ * K_];
__device__ unsigned int g_counter = 0;

__global__ __launch_bounds__(THREADS, 1)
void snn_main_kernel(const float* __restrict__ spikes,      // [B,T,NIN]
                     const float* __restrict__ w_ih,        // [H,NIN]
                     const float* __restrict__ delay_raw,   // [H,NIN]
                     const float* __restrict__ w_read,      // [H]
                     const float* __restrict__ b_read,      // scalar
                     const float* __restrict__ slot_mask,   // [K,T]
                     float* __restrict__ out)               // [B,K]
{
    extern __shared__ char smem_raw[];
    float*  I_sh    = (float*)smem_raw;                       // 2 copies [TPAD][HB]: 135168 B
    float2* wp_sh   = (float2*)(I_sh + 2*ICOPY);              // [NIN][HB]  65536 B
    unsigned char* s_sh = (unsigned char*)(wp_sh + NIN_*HB_); // [NIN][HB]   8192 B
    unsigned int* maskA = (unsigned int*)(s_sh + NIN_*HB_);   // [T][2]      1024 B
    unsigned long long* colbits = (unsigned long long*)(maskA + T_*2); // [2][NIN] 1024 B
    unsigned int* maskS = (unsigned int*)(colbits + 2*NIN_);  // [K][4] bitmask  64 B
    float*  red     = (float*)(maskS + K_*4);                 // 16 floats

    __shared__ int is_last;

    const int tid = threadIdx.x;
    const int hb  = blockIdx.x;
    const int b   = blockIdx.y;

    // ---- zero both I copies (incl. dump rows), vectorized ----
    {
        float4* I4 = (float4*)I_sh;
        #pragma unroll
        for (int r = tid; r < (2*ICOPY)/4; r += THREADS)
            I4[r] = make_float4(0.f, 0.f, 0.f, 0.f);
    }

    // ---- slot mask -> 4x128-bit register-style bitmask via ballot ----
    {
        #pragma unroll
        for (int rep = 0; rep < (K_*T_)/THREADS; rep++) {
            int idx = rep*THREADS + tid;
            float v = slot_mask[idx];
            unsigned int ball = __ballot_sync(0xFFFFFFFFu, v != 0.f);
            if ((tid & 31) == 0) maskS[idx >> 5] = ball;
        }
    }

    // ---- Phase A: per-timestep 64-bit active-input masks (deterministic ballots) ----
    {
        const float* xb = spikes + (size_t)b * T_ * NIN_;
        #pragma unroll
        for (int rep = 0; rep < (T_*NIN_)/THREADS; rep++) {
            int idx = rep*THREADS + tid;           // t = idx>>6, i = idx&63
            float v = xb[idx];
            unsigned int ball = __ballot_sync(0xFFFFFFFFu, v != 0.f);
            if ((tid & 31) == 0) {
                int t = idx >> 6;
                int half = (idx >> 5) & 1;
                maskA[t*2 + half] = ball;
            }
        }
    }

    // ---- Phase 1c: tap params, transposed [i][h] layout ----
    {
        const int gbase = hb * HB_ * NIN_;
        #pragma unroll
        for (int rep = 0; rep < (HB_*NIN_)/THREADS; rep++) {
            int idx = rep*THREADS + tid;
            int hh = idx >> 6;
            int ii = idx & 63;
            float raw  = delay_raw[gbase + idx];
            float w    = w_ih[gbase + idx];
            float d    = (float)DMAX_ / (1.f + expf(-raw));  // sigmoid * DMAX
            float d0   = floorf(d);
            float frac = d - d0;
            int   s0   = (int)d0 + 1;                        // read-before-insert => +1
            wp_sh[ii*HB_ + hh] = make_float2(w*(1.f-frac), w*frac);
            s_sh [ii*HB_ + hh] = (unsigned char)s0;
        }
    }
    __syncthreads();

    // ---- Phase A2: bit-transpose -> per-column 64-bit masks (broadcast LDS) ----
    if (tid < 2*NIN_) {
        int i    = tid & (NIN_-1);
        int half = tid >> 6;               // t-half: bits t' in [half*64, half*64+64)
        int wsel = i >> 5;
        int shft = i & 31;
        unsigned long long bits = 0ull;
        #pragma unroll
        for (int tb = 0; tb < 64; tb++) {
            unsigned int mw = maskA[(half*64 + tb)*2 + wsel];
            bits |= (unsigned long long)((mw >> shft) & 1u) << tb;
        }
        colbits[half*NIN_ + i] = bits;
    }
    __syncthreads();

    // ---- Phase B: column-driven batched scatter (all 256 threads) ----
    {
        const int grp = tid >> 7;                 // 0: columns 0..31, 1: columns 32..63
        const int h   = tid & (HB_-1);
        float* __restrict__ Ic = I_sh + grp * ICOPY;
        #pragma unroll 1
        for (int ci = 0; ci < 32; ci++) {
            const int i = grp*32 + ci;
            const float2 w  = wp_sh[i*HB_ + h];
            const int   s0  = (int)s_sh[i*HB_ + h];
            const int   s1  = min(s0 + 1, DMAX_ + 1);
            #pragma unroll
            for (int half = 0; half < 2; half++) {
                unsigned long long m = colbits[half*NIN_ + i];
                const int tb = half * 64;
                while (m) {
                    int b0 = __ffsll(m) - 1;            m &= m - 1;
                    int b1 = m ? __ffsll(m) - 1 : 255;  m &= m - 1;
                    int b2 = m ? __ffsll(m) - 1 : 255;  m &= m - 1;
                    int b3 = m ? __ffsll(m) - 1 : 255;  m &= m - 1;
                    // tap0 sub-batch (rows distinct by construction)
                    int r0 = min(b0 + tb + s0, T_ + 0);
                    int r1 = min(b1 + tb + s0, T_ + 1);
                    int r2 = min(b2 + tb + s0, T_ + 2);
                    int r3 = min(b3 + tb + s0, T_ + 3);
                    float a0 = Ic[r0*HB_ + h];
                    float a1 = Ic[r1*HB_ + h];
                    float a2 = Ic[r2*HB_ + h];
                    float a3 = Ic[r3*HB_ + h];
                    Ic[r0*HB_ + h] = a0 + w.x;
                    Ic[r1*HB_ + h] = a1 + w.x;
                    Ic[r2*HB_ + h] = a2 + w.x;
                    Ic[r3*HB_ + h] = a3 + w.x;
                    // tap1 sub-batch
                    int q0 = min(b0 + tb + s1, T_ + 0);
                    int q1 = min(b1 + tb + s1, T_ + 1);
                    int q2 = min(b2 + tb + s1, T_ + 2);
                    int q3 = min(b3 + tb + s1, T_ + 3);
                    float c0 = Ic[q0*HB_ + h];
                    float c1 = Ic[q1*HB_ + h];
                    float c2 = Ic[q2*HB_ + h];
                    float c3 = Ic[q3*HB_ + h];
                    Ic[q0*HB_ + h] = c0 + w.y;
                    Ic[q1*HB_ + h] = c1 + w.y;
                    Ic[q2*HB_ + h] = c2 + w.y;
                    Ic[q3*HB_ + h] = c3 + w.y;
                }
            }
        }
    }
    __syncthreads();

    // ---- Phase 3: LIF scan, spikes -> bitmask; popcount readout ----
    if (tid < HB_) {
        float v = 0.f;       // VRESET
        int   ref = 0;
        unsigned int sb0 = 0u, sb1 = 0u, sb2 = 0u, sb3 = 0u;
        #pragma unroll
        for (int t = 0; t < T_; t++) {
            float I  = I_sh[t*HB_ + tid] + I_sh[ICOPY + t*HB_ + tid];
            bool  nr = (ref <= 0);
            float vn = nr ? (v + 0.1f * (I - v)) : v;            // DT/TAU=0.1, VRESET=0
            bool  spk = nr && (vn - 1.0f >= 0.f);                // spike_fn(v-THR)*not_ref
            v   = spk ? 0.f : vn;
            ref = spk ? 2 : max(ref - 1, 0);
            unsigned int bit = spk ? 1u : 0u;
            if (t < 32)       sb0 |= bit << t;
            else if (t < 64)  sb1 |= bit << (t - 32);
            else if (t < 96)  sb2 |= bit << (t - 64);
            else              sb3 |= bit << (t - 96);
        }

        float wr = w_read[hb*HB_ + tid];
        float c0, c1, c2, c3;
        {
            // a_k = popc(spikebits & maskbits_k): exact == float accumulation of 0/1
            int n0 = __popc(sb0 & maskS[0*4+0]) + __popc(sb1 & maskS[0*4+1])
                   + __popc(sb2 & maskS[0*4+2]) + __popc(sb3 & maskS[0*4+3]);
            int n1 = __popc(sb0 & maskS[1*4+0]) + __popc(sb1 & maskS[1*4+1])
                   + __popc(sb2 & maskS[1*4+2]) + __popc(sb3 & maskS[1*4+3]);
            int n2 = __popc(sb0 & maskS[2*4+0]) + __popc(sb1 & maskS[2*4+1])
                   + __popc(sb2 & maskS[2*4+2]) + __popc(sb3 & maskS[2*4+3]);
            int n3 = __popc(sb0 & maskS[3*4+0]) + __popc(sb1 & maskS[3*4+1])
                   + __popc(sb2 & maskS[3*4+2]) + __popc(sb3 & maskS[3*4+3]);
            c0 = (float)n0 * wr;
            c1 = (float)n1 * wr;
            c2 = (float)n2 * wr;
            c3 = (float)n3 * wr;
        }
        #pragma unroll
        for (int off = 16; off; off >>= 1) {
            c0 += __shfl_down_sync(0xFFFFFFFFu, c0, off);
            c1 += __shfl_down_sync(0xFFFFFFFFu, c1, off);
            c2 += __shfl_down_sync(0xFFFFFFFFu, c2, off);
            c3 += __shfl_down_sync(0xFFFFFFFFu, c3, off);
        }
        int lane = tid & 31, warp = tid >> 5;
        if (lane == 0) {
            red[warp*4 + 0] = c0;
            red[warp*4 + 1] = c1;
            red[warp*4 + 2] = c2;
            red[warp*4 + 3] = c3;
        }
    }
    __syncthreads();
    if (tid < K_) {
        float s = red[tid] + red[4 + tid] + red[8 + tid] + red[12 + tid];
        g_partials[(b*NHB_ + hb)*K_ + tid] = s;
    }
    __syncthreads();

    // ---- fused deterministic final reduction: last block writes output ----
    if (tid == 0) {
        __threadfence();
        unsigned int done = atomicAdd(&g_counter, 1u);
        is_last = (done == NBLK - 1) ? 1 : 0;
    }
    __syncthreads();
    if (is_last) {
        if (tid == 0) g_counter = 0;   // reset for next graph replay
        __threadfence();
        if (tid < B_ * K_) {
            int bb = tid >> 2, kk = tid & 3;
            float s = b_read[0];
            #pragma unroll
            for (int h2 = 0; h2 < NHB_; h2++)
                s += __ldcg(&g_partials[(bb*NHB_ + h2)*K_ + kk]);
            out[bb*K_ + kk] = s;
        }
    }
}

extern "C" void kernel_launch(void* const* d_in, const int* in_sizes, int n_in,
                              void* d_out, int out_size)
{
    (void)in_sizes; (void)n_in; (void)out_size;
    const float* spikes    = (const float*)d_in[0];   // [32,128,64]
    const float* w_ih      = (const float*)d_in[1];   // [512,64]
    const float* delay_raw = (const float*)d_in[2];   // [512,64]
    const float* w_read    = (const float*)d_in[3];   // [512]
    const float* b_read    = (const float*)d_in[4];   // scalar
    const float* slot_mask = (const float*)d_in[5];   // [4,128]

    const size_t SMEM = (size_t)2*ICOPY*4             // 2 I copies   135168
                      + (size_t)NIN_*HB_*8            // wp (float2)   65536
                      + (size_t)NIN_*HB_              // s (u8)         8192
                      + (size_t)T_*2*4                // maskA          1024
                      + (size_t)2*NIN_*8              // colbits        1024
                      + (size_t)K_*4*4                // maskS            64
                      + 16*4;                         // red
    cudaFuncSetAttribute(snn_main_kernel,
                         cudaFuncAttributeMaxDynamicSharedMemorySize, (int)SMEM);

    dim3 grid(NHB_, B_);
    snn_main_kernel<<<grid, THREADS, SMEM>>>(spikes, w_ih, delay_raw, w_read,
                                             b_read, slot_mask, (float*)d_out);
}

// round 7
// speedup vs baseline: 1.2960x; 1.2105x over previous
#include <cuda_runtime.h>
#include <cstdint>

#define B_    32
#define T_    128
#define NIN_  64
#define H_    512
#define DMAX_ 50
#define K_    4
#define HB_   128           // h per block
#define NHB_  (H_/HB_)      // 4 h-tiles
#define THREADS 256
#define NBLK  (B_ * NHB_)   // 128

#define TPAD  132                 // 128 real rows + 4 per-slot clamp rows
#define CAP_  32                  // event-list capacity per column

// deterministic partial sums: [b][hb][k]
__device__ float g_partials[B_ * NHB_ * K_];
__device__ unsigned int g_counter = 0;

// packed fp32x2 add (Blackwell)
__device__ __forceinline__ unsigned long long addf32x2(unsigned long long a, unsigned long long b) {
    unsigned long long r;
    asm("add.rn.f32x2 %0, %1, %2;" : "=l"(r) : "l"(a), "l"(b));
    return r;
}

__global__ __launch_bounds__(THREADS, 1)
void snn_main_kernel(const float* __restrict__ spikes,      // [B,T,NIN]
                     const float* __restrict__ w_ih,        // [H,NIN]
                     const float* __restrict__ delay_raw,   // [H,NIN]
                     const float* __restrict__ w_read,      // [H]
                     const float* __restrict__ b_read,      // scalar
                     const float* __restrict__ slot_mask,   // [K,T]
                     float* __restrict__ out)               // [B,K]
{
    extern __shared__ char smem_raw[];
    // I2: pair accumulator. row t holds (tap0 contribution @t, tap1 contribution @t+1)
    unsigned long long* I2  = (unsigned long long*)smem_raw;          // [TPAD][HB] u64  135168 B
    unsigned long long* wpu = I2 + TPAD*HB_;                          // [NIN][HB] (wx,wy) 65536 B
    unsigned char* s_sh = (unsigned char*)(wpu + NIN_*HB_);           // [NIN][HB]          8192 B
    unsigned long long* colbits = (unsigned long long*)(s_sh + NIN_*HB_); // [2][NIN]       1024 B
    unsigned int* maskA = (unsigned int*)(colbits + 2*NIN_);          // [T][2]             1024 B
    unsigned int* kcnt  = maskA + T_*2;                               // [NIN]               256 B
    unsigned int* maskS = kcnt + NIN_;                                // [K][4]               64 B
    float* red          = (float*)(maskS + K_*4);                     // 16 floats            64 B
    unsigned char* tpos = (unsigned char*)(red + 16);                 // [NIN][CAP_]        2048 B

    __shared__ int is_last;

    const int tid = threadIdx.x;
    const int hb  = blockIdx.x;
    const int b   = blockIdx.y;

    // ---- zero I2 (vectorized) + prefill tpos sentinels ----
    {
        float4* I4 = (float4*)I2;
        #pragma unroll
        for (int r = tid; r < (TPAD*HB_*8)/16; r += THREADS)
            I4[r] = make_float4(0.f, 0.f, 0.f, 0.f);
        unsigned int* tp32 = (unsigned int*)tpos;
        #pragma unroll
        for (int j = tid; j < (NIN_*CAP_)/4; j += THREADS)
            tp32[j] = 0xFFFFFFFFu;
    }

    // ---- slot mask -> 4x128-bit bitmask via ballot ----
    {
        #pragma unroll
        for (int rep = 0; rep < (K_*T_)/THREADS; rep++) {
            int idx = rep*THREADS + tid;
            float v = slot_mask[idx];
            unsigned int ball = __ballot_sync(0xFFFFFFFFu, v != 0.f);
            if ((tid & 31) == 0) maskS[idx >> 5] = ball;
        }
    }

    // ---- Phase A: per-timestep active-input masks (deterministic ballots) ----
    {
        const float* xb = spikes + (size_t)b * T_ * NIN_;
        #pragma unroll
        for (int rep = 0; rep < (T_*NIN_)/THREADS; rep++) {
            int idx = rep*THREADS + tid;           // t = idx>>6, i = idx&63
            float v = xb[idx];
            unsigned int ball = __ballot_sync(0xFFFFFFFFu, v != 0.f);
            if ((tid & 31) == 0) {
                int t = idx >> 6;
                int half = (idx >> 5) & 1;
                maskA[t*2 + half] = ball;
            }
        }
    }

    // ---- Phase 1c: tap params -> folded (wx, wy) pair + shift, [i][h] layout ----
    {
        const int gbase = hb * HB_ * NIN_;
        #pragma unroll
        for (int rep = 0; rep < (HB_*NIN_)/THREADS; rep++) {
            int idx = rep*THREADS + tid;
            int hh = idx >> 6;
            int ii = idx & 63;
            float raw  = delay_raw[gbase + idx];
            float w    = w_ih[gbase + idx];
            float d    = (float)DMAX_ / (1.f + expf(-raw));  // sigmoid * DMAX
            float d0   = floorf(d);
            float frac = d - d0;
            int   i0   = (int)d0;
            int   s0   = i0 + 1;                             // read-before-insert => +1
            float w0 = w * (1.f - frac), w1 = w * frac;
            bool  cap = (i0 >= DMAX_);                       // i1==i0: both taps same slot
            float wx = cap ? (w0 + w1) : w0;
            float wy = cap ? 0.f : w1;
            wpu[ii*HB_ + hh] = ((unsigned long long)__float_as_uint(wy) << 32)
                             | (unsigned long long)__float_as_uint(wx);
            s_sh[ii*HB_ + hh] = (unsigned char)s0;
        }
    }
    __syncthreads();

    // ---- Phase A2: bit-transpose -> per-column 64-bit masks ----
    if (tid < 2*NIN_) {
        int i    = tid & (NIN_-1);
        int half = tid >> 6;
        int wsel = i >> 5;
        int shft = i & 31;
        unsigned long long bits = 0ull;
        #pragma unroll
        for (int tb = 0; tb < 64; tb++) {
            unsigned int mw = maskA[(half*64 + tb)*2 + wsel];
            bits |= (unsigned long long)((mw >> shft) & 1u) << tb;
        }
        colbits[half*NIN_ + i] = bits;
    }
    __syncthreads();

    // ---- Phase A3: decode set-bit positions ONCE per column (shared across h) ----
    if (tid < NIN_) {
        int ci = tid;
        unsigned long long lo = colbits[ci];
        unsigned long long hi = colbits[NIN_ + ci];
        int k = __popcll(lo) + __popcll(hi);
        kcnt[ci] = (unsigned int)k;
        int n = 0;
        unsigned long long m = lo;
        while (m && n < CAP_) { int p = __ffsll(m) - 1; m &= m - 1; tpos[ci*CAP_ + n] = (unsigned char)p; n++; }
        m = hi;
        while (m && n < CAP_) { int p = __ffsll(m) - 1; m &= m - 1; tpos[ci*CAP_ + n] = (unsigned char)(64 + p); n++; }
    }
    __syncthreads();

    // ---- Phase B: event-list scatter, pair accumulator, load-first batches ----
    // Within a column, targets t'+s0 are strictly increasing (same shift, distinct
    // bits; clamps 128..131 also increasing) -> batch of 4 rows always distinct ->
    // loads-before-stores is safe. Sentinel 0xFF clamps into its slot's dump row.
    if (tid < HB_) {
        const int h = tid;
        #pragma unroll 1
        for (int ci = 0; ci < NIN_; ci++) {
            const unsigned long long wb = wpu[ci*HB_ + h];
            const int s0 = (int)s_sh[ci*HB_ + h];
            const int k  = (int)kcnt[ci];
            const int kb = min(k, CAP_);
            const unsigned char* tp = tpos + ci*CAP_;
            #pragma unroll 1
            for (int e = 0; e < kb; e += 4) {
                unsigned int p4 = *(const unsigned int*)(tp + e);
                int r0 = min((int)(p4 & 255u)         + s0, T_ + 0);
                int r1 = min((int)((p4 >> 8) & 255u)  + s0, T_ + 1);
                int r2 = min((int)((p4 >> 16) & 255u) + s0, T_ + 2);
                int r3 = min((int)(p4 >> 24)          + s0, T_ + 3);
                unsigned long long a0 = I2[r0*HB_ + h];
                unsigned long long a1 = I2[r1*HB_ + h];
                unsigned long long a2 = I2[r2*HB_ + h];
                unsigned long long a3 = I2[r3*HB_ + h];
                I2[r0*HB_ + h] = addf32x2(a0, wb);
                I2[r1*HB_ + h] = addf32x2(a1, wb);
                I2[r2*HB_ + h] = addf32x2(a2, wb);
                I2[r3*HB_ + h] = addf32x2(a3, wb);
            }
            if (k > CAP_) {                      // exact fallback, ~never taken
                unsigned long long lo = colbits[ci], hi2 = colbits[NIN_ + ci];
                int rem = CAP_;
                while (rem && lo)  { lo  &= lo  - 1; rem--; }
                while (rem && hi2) { hi2 &= hi2 - 1; rem--; }
                while (lo)  { int t = __ffsll(lo) - 1;      lo  &= lo  - 1;
                              int r = min(t + s0, T_);
                              I2[r*HB_ + h] = addf32x2(I2[r*HB_ + h], wb); }
                while (hi2) { int t = 64 + __ffsll(hi2) - 1; hi2 &= hi2 - 1;
                              int r = min(t + s0, T_);
                              I2[r*HB_ + h] = addf32x2(I2[r*HB_ + h], wb); }
            }
        }
    }
    __syncthreads();

    // ---- Phase 3: LIF scan (I[t] = pair[t].x + pair[t-1].y), popcount readout ----
    if (tid < HB_) {
        const float2* I2f = (const float2*)I2;
        float v = 0.f;       // VRESET
        int   ref = 0;
        float prevy = 0.f;
        unsigned int sb0 = 0u, sb1 = 0u, sb2 = 0u, sb3 = 0u;
        #pragma unroll
        for (int t = 0; t < T_; t++) {
            float2 c = I2f[t*HB_ + tid];
            float I  = c.x + prevy;
            prevy = c.y;
            bool  nr = (ref <= 0);
            float vn = nr ? (v + 0.1f * (I - v)) : v;            // DT/TAU=0.1, VRESET=0
            bool  spk = nr && (vn - 1.0f >= 0.f);                // spike_fn(v-THR)*not_ref
            v   = spk ? 0.f : vn;
            ref = spk ? 2 : max(ref - 1, 0);
            unsigned int bit = spk ? 1u : 0u;
            if (t < 32)       sb0 |= bit << t;
            else if (t < 64)  sb1 |= bit << (t - 32);
            else if (t < 96)  sb2 |= bit << (t - 64);
            else              sb3 |= bit << (t - 96);
        }

        float wr = w_read[hb*HB_ + tid];
        int n0 = __popc(sb0 & maskS[0])  + __popc(sb1 & maskS[1])
               + __popc(sb2 & maskS[2])  + __popc(sb3 & maskS[3]);
        int n1 = __popc(sb0 & maskS[4])  + __popc(sb1 & maskS[5])
               + __popc(sb2 & maskS[6])  + __popc(sb3 & maskS[7]);
        int n2 = __popc(sb0 & maskS[8])  + __popc(sb1 & maskS[9])
               + __popc(sb2 & maskS[10]) + __popc(sb3 & maskS[11]);
        int n3 = __popc(sb0 & maskS[12]) + __popc(sb1 & maskS[13])
               + __popc(sb2 & maskS[14]) + __popc(sb3 & maskS[15]);
        float c0 = (float)n0 * wr;
        float c1 = (float)n1 * wr;
        float c2 = (float)n2 * wr;
        float c3 = (float)n3 * wr;
        #pragma unroll
        for (int off = 16; off; off >>= 1) {
            c0 += __shfl_down_sync(0xFFFFFFFFu, c0, off);
            c1 += __shfl_down_sync(0xFFFFFFFFu, c1, off);
            c2 += __shfl_down_sync(0xFFFFFFFFu, c2, off);
            c3 += __shfl_down_sync(0xFFFFFFFFu, c3, off);
        }
        int lane = tid & 31, warp = tid >> 5;
        if (lane == 0) {
            red[warp*4 + 0] = c0;
            red[warp*4 + 1] = c1;
            red[warp*4 + 2] = c2;
            red[warp*4 + 3] = c3;
        }
    }
    __syncthreads();
    if (tid < K_) {
        float s = red[tid] + red[4 + tid] + red[8 + tid] + red[12 + tid];
        g_partials[(b*NHB_ + hb)*K_ + tid] = s;
    }
    __syncthreads();

    // ---- fused deterministic final reduction: last block writes output ----
    if (tid == 0) {
        __threadfence();
        unsigned int done = atomicAdd(&g_counter, 1u);
        is_last = (done == NBLK - 1) ? 1 : 0;
    }
    __syncthreads();
    if (is_last) {
        if (tid == 0) g_counter = 0;   // reset for next graph replay
        __threadfence();
        if (tid < B_ * K_) {
            int bb = tid >> 2, kk = tid & 3;
            float s = b_read[0];
            #pragma unroll
            for (int h2 = 0; h2 < NHB_; h2++)
                s += __ldcg(&g_partials[(bb*NHB_ + h2)*K_ + kk]);
            out[bb*K_ + kk] = s;
        }
    }
}

extern "C" void kernel_launch(void* const* d_in, const int* in_sizes, int n_in,
                              void* d_out, int out_size)
{
    (void)in_sizes; (void)n_in; (void)out_size;
    const float* spikes    = (const float*)d_in[0];   // [32,128,64]
    const float* w_ih      = (const float*)d_in[1];   // [512,64]
    const float* delay_raw = (const float*)d_in[2];   // [512,64]
    const float* w_read    = (const float*)d_in[3];   // [512]
    const float* b_read    = (const float*)d_in[4];   // scalar
    const float* slot_mask = (const float*)d_in[5];   // [4,128]

    const size_t SMEM = (size_t)TPAD*HB_*8            // I2 pairs     135168
                      + (size_t)NIN_*HB_*8            // wpu (wx,wy)   65536
                      + (size_t)NIN_*HB_              // s (u8)         8192
                      + (size_t)2*NIN_*8              // colbits        1024
                      + (size_t)T_*2*4                // maskA          1024
                      + (size_t)NIN_*4                // kcnt            256
                      + (size_t)K_*4*4                // maskS            64
                      + 16*4                          // red              64
                      + (size_t)NIN_*CAP_;            // tpos           2048
    cudaFuncSetAttribute(snn_main_kernel,
                         cudaFuncAttributeMaxDynamicSharedMemorySize, (int)SMEM);

    dim3 grid(NHB_, B_);
    snn_main_kernel<<<grid, THREADS, SMEM>>>(spikes, w_ih, delay_raw, w_read,
                                             b_read, slot_mask, (float*)d_out);
}

// round 8
// speedup vs baseline: 1.3532x; 1.0441x over previous
#include <cuda_runtime.h>
#include <cstdint>

#define B_    32
#define T_    128
#define NIN_  64
#define H_    512
#define DMAX_ 50
#define K_    4
#define HB_   64            // h per block
#define NHB_  (H_/HB_)      // 8 h-tiles
#define THREADS 256
#define NBLK  (B_ * NHB_)   // 256

#define TPAD  132                 // 128 real rows + 4 per-slot clamp rows
#define CAP_  32                  // event-list capacity per column

// deterministic partial sums: [b][hb][k]
__device__ float g_partials[B_ * NHB_ * K_];
__device__ unsigned int g_counter = 0;

// packed fp32x2 add (Blackwell)
__device__ __forceinline__ unsigned long long addf32x2(unsigned long long a, unsigned long long b) {
    unsigned long long r;
    asm("add.rn.f32x2 %0, %1, %2;" : "=l"(r) : "l"(a), "l"(b));
    return r;
}

__global__ __launch_bounds__(THREADS, 2)
void snn_main_kernel(const float* __restrict__ spikes,      // [B,T,NIN]
                     const float* __restrict__ w_ih,        // [H,NIN]
                     const float* __restrict__ delay_raw,   // [H,NIN]
                     const float* __restrict__ w_read,      // [H]
                     const float* __restrict__ b_read,      // scalar
                     const float* __restrict__ slot_mask,   // [K,T]
                     float* __restrict__ out)               // [B,K]
{
    extern __shared__ char smem_raw[];
    // I2: pair accumulator. row t holds (tap0 contribution @t, tap1 contribution @t+1)
    unsigned long long* I2  = (unsigned long long*)smem_raw;          // [TPAD][HB] u64   67584 B
    unsigned long long* wpu = I2 + TPAD*HB_;                          // [NIN][HB] (wx,wy) 32768 B
    unsigned char* s_sh = (unsigned char*)(wpu + NIN_*HB_);           // [NIN][HB]          4096 B
    unsigned long long* colbits = (unsigned long long*)(s_sh + NIN_*HB_); // [2][NIN]       1024 B
    unsigned int* maskA = (unsigned int*)(colbits + 2*NIN_);          // [T][2]             1024 B
    unsigned int* kcnt  = maskA + T_*2;                               // [NIN]               256 B
    unsigned int* maskS = kcnt + NIN_;                                // [K][4]               64 B
    float* red          = (float*)(maskS + K_*4);                     // 8 floats             32 B
    unsigned char* tpos = (unsigned char*)(red + 8);                  // [NIN][CAP_]        2048 B

    __shared__ int is_last;

    const int tid = threadIdx.x;
    const int hb  = blockIdx.x;
    const int b   = blockIdx.y;

    // ---- zero I2 (vectorized) + prefill tpos sentinels ----
    {
        float4* I4 = (float4*)I2;
        for (int r = tid; r < (TPAD*HB_*8)/16; r += THREADS)
            I4[r] = make_float4(0.f, 0.f, 0.f, 0.f);
        unsigned int* tp32 = (unsigned int*)tpos;
        #pragma unroll
        for (int j = tid; j < (NIN_*CAP_)/4; j += THREADS)
            tp32[j] = 0xFFFFFFFFu;
    }

    // ---- slot mask -> 4x128-bit bitmask via ballot ----
    {
        #pragma unroll
        for (int rep = 0; rep < (K_*T_)/THREADS; rep++) {
            int idx = rep*THREADS + tid;
            float v = slot_mask[idx];
            unsigned int ball = __ballot_sync(0xFFFFFFFFu, v != 0.f);
            if ((tid & 31) == 0) maskS[idx >> 5] = ball;
        }
    }

    // ---- Phase A: per-timestep active-input masks (deterministic ballots) ----
    {
        const float* xb = spikes + (size_t)b * T_ * NIN_;
        #pragma unroll
        for (int rep = 0; rep < (T_*NIN_)/THREADS; rep++) {
            int idx = rep*THREADS + tid;           // t = idx>>6, i = idx&63
            float v = xb[idx];
            unsigned int ball = __ballot_sync(0xFFFFFFFFu, v != 0.f);
            if ((tid & 31) == 0) {
                int t = idx >> 6;
                int half = (idx >> 5) & 1;
                maskA[t*2 + half] = ball;
            }
        }
    }

    // ---- Phase 1c: tap params -> folded (wx, wy) pair + shift, [i][h] layout ----
    {
        const int gbase = hb * HB_ * NIN_;
        #pragma unroll
        for (int rep = 0; rep < (HB_*NIN_)/THREADS; rep++) {
            int idx = rep*THREADS + tid;
            int hh = idx >> 6;
            int ii = idx & 63;
            float raw  = delay_raw[gbase + idx];
            float w    = w_ih[gbase + idx];
            float d    = (float)DMAX_ / (1.f + expf(-raw));  // sigmoid * DMAX
            float d0   = floorf(d);
            float frac = d - d0;
            int   i0   = (int)d0;
            int   s0   = i0 + 1;                             // read-before-insert => +1
            float w0 = w * (1.f - frac), w1 = w * frac;
            bool  cap = (i0 >= DMAX_);                       // i1==i0: both taps same slot
            float wx = cap ? (w0 + w1) : w0;
            float wy = cap ? 0.f : w1;
            wpu[ii*HB_ + hh] = ((unsigned long long)__float_as_uint(wy) << 32)
                             | (unsigned long long)__float_as_uint(wx);
            s_sh[ii*HB_ + hh] = (unsigned char)s0;
        }
    }
    __syncthreads();

    // ---- Phase A2: bit-transpose -> per-column 64-bit masks ----
    if (tid < 2*NIN_) {
        int i    = tid & (NIN_-1);
        int half = tid >> 6;
        int wsel = i >> 5;
        int shft = i & 31;
        unsigned long long bits = 0ull;
        #pragma unroll
        for (int tb = 0; tb < 64; tb++) {
            unsigned int mw = maskA[(half*64 + tb)*2 + wsel];
            bits |= (unsigned long long)((mw >> shft) & 1u) << tb;
        }
        colbits[half*NIN_ + i] = bits;
    }
    __syncthreads();

    // ---- Phase A3: decode set-bit positions ONCE per column (shared across h) ----
    if (tid < NIN_) {
        int ci = tid;
        unsigned long long lo = colbits[ci];
        unsigned long long hi = colbits[NIN_ + ci];
        int k = __popcll(lo) + __popcll(hi);
        kcnt[ci] = (unsigned int)k;
        int n = 0;
        unsigned long long m = lo;
        while (m && n < CAP_) { int p = __ffsll(m) - 1; m &= m - 1; tpos[ci*CAP_ + n] = (unsigned char)p; n++; }
        m = hi;
        while (m && n < CAP_) { int p = __ffsll(m) - 1; m &= m - 1; tpos[ci*CAP_ + n] = (unsigned char)(64 + p); n++; }
    }
    __syncthreads();

    // ---- Phase B: event-list scatter, pair accumulator, load-first batches ----
    // Within a column, targets t'+s0 are strictly increasing (same shift, distinct
    // bits; clamps 128..131 also increasing) -> batch of 4 rows always distinct ->
    // loads-before-stores is safe. Sentinel 0xFF clamps into its slot's dump row.
    if (tid < HB_) {
        const int h = tid;
        #pragma unroll 1
        for (int ci = 0; ci < NIN_; ci++) {
            const unsigned long long wb = wpu[ci*HB_ + h];
            const int s0 = (int)s_sh[ci*HB_ + h];
            const int k  = (int)kcnt[ci];
            const int kb = min(k, CAP_);
            const unsigned char* tp = tpos + ci*CAP_;
            #pragma unroll 1
            for (int e = 0; e < kb; e += 4) {
                unsigned int p4 = *(const unsigned int*)(tp + e);
                int r0 = min((int)(p4 & 255u)         + s0, T_ + 0);
                int r1 = min((int)((p4 >> 8) & 255u)  + s0, T_ + 1);
                int r2 = min((int)((p4 >> 16) & 255u) + s0, T_ + 2);
                int r3 = min((int)(p4 >> 24)          + s0, T_ + 3);
                unsigned long long a0 = I2[r0*HB_ + h];
                unsigned long long a1 = I2[r1*HB_ + h];
                unsigned long long a2 = I2[r2*HB_ + h];
                unsigned long long a3 = I2[r3*HB_ + h];
                I2[r0*HB_ + h] = addf32x2(a0, wb);
                I2[r1*HB_ + h] = addf32x2(a1, wb);
                I2[r2*HB_ + h] = addf32x2(a2, wb);
                I2[r3*HB_ + h] = addf32x2(a3, wb);
            }
            if (k > CAP_) {                      // exact fallback, ~never taken
                unsigned long long lo = colbits[ci], hi2 = colbits[NIN_ + ci];
                int rem = CAP_;
                while (rem && lo)  { lo  &= lo  - 1; rem--; }
                while (rem && hi2) { hi2 &= hi2 - 1; rem--; }
                while (lo)  { int t = __ffsll(lo) - 1;      lo  &= lo  - 1;
                              int r = min(t + s0, T_);
                              I2[r*HB_ + h] = addf32x2(I2[r*HB_ + h], wb); }
                while (hi2) { int t = 64 + __ffsll(hi2) - 1; hi2 &= hi2 - 1;
                              int r = min(t + s0, T_);
                              I2[r*HB_ + h] = addf32x2(I2[r*HB_ + h], wb); }
            }
        }
    }
    __syncthreads();

    // ---- Phase 3: LIF scan (I[t] = pair[t].x + pair[t-1].y), popcount readout ----
    if (tid < HB_) {
        const float2* I2f = (const float2*)I2;
        float v = 0.f;       // VRESET
        int   ref = 0;
        float prevy = 0.f;
        unsigned int sb0 = 0u, sb1 = 0u, sb2 = 0u, sb3 = 0u;
        #pragma unroll
        for (int t = 0; t < T_; t++) {
            float2 c = I2f[t*HB_ + tid];
            float I  = c.x + prevy;
            prevy = c.y;
            bool  nr = (ref <= 0);
            float vn = nr ? (v + 0.1f * (I - v)) : v;            // DT/TAU=0.1, VRESET=0
            bool  spk = nr && (vn - 1.0f >= 0.f);                // spike_fn(v-THR)*not_ref
            v   = spk ? 0.f : vn;
            ref = spk ? 2 : max(ref - 1, 0);
            unsigned int bit = spk ? 1u : 0u;
            if (t < 32)       sb0 |= bit << t;
            else if (t < 64)  sb1 |= bit << (t - 32);
            else if (t < 96)  sb2 |= bit << (t - 64);
            else              sb3 |= bit << (t - 96);
        }

        float wr = w_read[hb*HB_ + tid];
        int n0 = __popc(sb0 & maskS[0])  + __popc(sb1 & maskS[1])
               + __popc(sb2 & maskS[2])  + __popc(sb3 & maskS[3]);
        int n1 = __popc(sb0 & maskS[4])  + __popc(sb1 & maskS[5])
               + __popc(sb2 & maskS[6])  + __popc(sb3 & maskS[7]);
        int n2 = __popc(sb0 & maskS[8])  + __popc(sb1 & maskS[9])
               + __popc(sb2 & maskS[10]) + __popc(sb3 & maskS[11]);
        int n3 = __popc(sb0 & maskS[12]) + __popc(sb1 & maskS[13])
               + __popc(sb2 & maskS[14]) + __popc(sb3 & maskS[15]);
        float c0 = (float)n0 * wr;
        float c1 = (float)n1 * wr;
        float c2 = (float)n2 * wr;
        float c3 = (float)n3 * wr;
        #pragma unroll
        for (int off = 16; off; off >>= 1) {
            c0 += __shfl_down_sync(0xFFFFFFFFu, c0, off);
            c1 += __shfl_down_sync(0xFFFFFFFFu, c1, off);
            c2 += __shfl_down_sync(0xFFFFFFFFu, c2, off);
            c3 += __shfl_down_sync(0xFFFFFFFFu, c3, off);
        }
        int lane = tid & 31, warp = tid >> 5;   // warp 0 or 1
        if (lane == 0) {
            red[warp*4 + 0] = c0;
            red[warp*4 + 1] = c1;
            red[warp*4 + 2] = c2;
            red[warp*4 + 3] = c3;
        }
    }
    __syncthreads();
    if (tid < K_) {
        float s = red[tid] + red[4 + tid];
        g_partials[(b*NHB_ + hb)*K_ + tid] = s;
    }
    __syncthreads();

    // ---- fused deterministic final reduction: last block writes output ----
    if (tid == 0) {
        __threadfence();
        unsigned int done = atomicAdd(&g_counter, 1u);
        is_last = (done == NBLK - 1) ? 1 : 0;
    }
    __syncthreads();
    if (is_last) {
        if (tid == 0) g_counter = 0;   // reset for next graph replay
        __threadfence();
        if (tid < B_ * K_) {
            int bb = tid >> 2, kk = tid & 3;
            float s = b_read[0];
            #pragma unroll
            for (int h2 = 0; h2 < NHB_; h2++)
                s += __ldcg(&g_partials[(bb*NHB_ + h2)*K_ + kk]);
            out[bb*K_ + kk] = s;
        }
    }
}

extern "C" void kernel_launch(void* const* d_in, const int* in_sizes, int n_in,
                              void* d_out, int out_size)
{
    (void)in_sizes; (void)n_in; (void)out_size;
    const float* spikes    = (const float*)d_in[0];   // [32,128,64]
    const float* w_ih      = (const float*)d_in[1];   // [512,64]
    const float* delay_raw = (const float*)d_in[2];   // [512,64]
    const float* w_read    = (const float*)d_in[3];   // [512]
    const float* b_read    = (const float*)d_in[4];   // scalar
    const float* slot_mask = (const float*)d_in[5];   // [4,128]

    const size_t SMEM = (size_t)TPAD*HB_*8            // I2 pairs      67584
                      + (size_t)NIN_*HB_*8            // wpu (wx,wy)   32768
                      + (size_t)NIN_*HB_              // s (u8)         4096
                      + (size_t)2*NIN_*8              // colbits        1024
                      + (size_t)T_*2*4                // maskA          1024
                      + (size_t)NIN_*4                // kcnt            256
                      + (size_t)K_*4*4                // maskS            64
                      + 8*4                           // red              32
                      + (size_t)NIN_*CAP_;            // tpos           2048
    cudaFuncSetAttribute(snn_main_kernel,
                         cudaFuncAttributeMaxDynamicSharedMemorySize, (int)SMEM);

    dim3 grid(NHB_, B_);
    snn_main_kernel<<<grid, THREADS, SMEM>>>(spikes, w_ih, delay_raw, w_read,
                                             b_read, slot_mask, (float*)d_out);
}